// round 15
// baseline (speedup 1.0000x reference)
#include <cuda_runtime.h>
#include <cstdint>

// Problem constants
#define BATCH 4
#define SEQ   2048
#define EMB   1024
#define NHEAD 16
#define HDIM  64
#define C3    3072
#define ROWS  8192   // BATCH*SEQ

// Scratch (device globals — allocation-free rule). tf32 values stored as u32.
__device__ unsigned g_qkv[(size_t)ROWS * C3];   // 96 MB (tf32)
__device__ unsigned g_y[(size_t)ROWS * EMB];    // 32 MB (tf32)
__device__ unsigned g_xa[(size_t)ROWS * EMB];   // 32 MB (tf32 of x)
__device__ unsigned g_wa[(size_t)C3 * EMB];     // 12 MB (tf32 of W_attn^T, [3072][1024])
__device__ unsigned g_wp[(size_t)EMB * EMB];    //  4 MB (tf32 of W_proj^T, [1024][1024])

__device__ __forceinline__ unsigned f2tf32(float f) {
    unsigned r;
    asm("cvt.rna.tf32.f32 %0, %1;" : "=r"(r) : "f"(f));
    return r;
}

__device__ __forceinline__ void mma_tf32(
    float& c0, float& c1, float& c2, float& c3,
    unsigned a0, unsigned a1, unsigned a2, unsigned a3,
    unsigned b0, unsigned b1)
{
    asm volatile(
        "mma.sync.aligned.m16n8k8.row.col.f32.tf32.tf32.f32 "
        "{%0,%1,%2,%3}, {%4,%5,%6,%7}, {%8,%9}, {%0,%1,%2,%3};\n"
        : "+f"(c0), "+f"(c1), "+f"(c2), "+f"(c3)
        : "r"(a0), "r"(a1), "r"(a2), "r"(a3), "r"(b0), "r"(b1));
}

__device__ __forceinline__ void ldsm_x4(
    unsigned& r0, unsigned& r1, unsigned& r2, unsigned& r3, uint32_t saddr)
{
    asm volatile(
        "ldmatrix.sync.aligned.m8n8.x4.shared.b16 {%0,%1,%2,%3}, [%4];\n"
        : "=r"(r0), "=r"(r1), "=r"(r2), "=r"(r3) : "r"(saddr));
}

__device__ __forceinline__ void cp_async16(unsigned saddr, const void* g) {
    asm volatile("cp.async.cg.shared.global [%0], [%1], 16;\n"
                 :: "r"(saddr), "l"(g));
}
__device__ __forceinline__ void cp_commit() {
    asm volatile("cp.async.commit_group;\n");
}
template <int N>
__device__ __forceinline__ void cp_wait() {
    asm volatile("cp.async.wait_group %0;\n" :: "n"(N));
}

// ---------------------------------------------------------------------------
// Pre-pass kernels
// ---------------------------------------------------------------------------
__global__ void cvt_tf32_kernel(const float4* __restrict__ in,
                                uint4* __restrict__ out, int n4)
{
    int i = blockIdx.x * blockDim.x + threadIdx.x;
    if (i < n4) {
        float4 v = in[i];
        out[i] = make_uint4(f2tf32(v.x), f2tf32(v.y), f2tf32(v.z), f2tf32(v.w));
    }
}

// out[n][k] = tf32(in[k][n]); in is [K][N] row-major. block (32,8), grid (N/32, K/32)
__global__ void transpose_tf32_kernel(const float* __restrict__ in,
                                      unsigned* __restrict__ out, int K, int N)
{
    __shared__ unsigned t[32][33];
    int n0 = blockIdx.x * 32, k0 = blockIdx.y * 32;
    int tx = threadIdx.x, ty = threadIdx.y;
#pragma unroll
    for (int i = 0; i < 32; i += 8)
        t[ty + i][tx] = f2tf32(in[(size_t)(k0 + ty + i) * N + n0 + tx]);
    __syncthreads();
#pragma unroll
    for (int i = 0; i < 32; i += 8)
        out[(size_t)(n0 + ty + i) * K + k0 + tx] = t[tx][ty + i];
}

// ---------------------------------------------------------------------------
// tf32 tensor-core GEMM with bias, cp.async 2-stage (R9-proven ordering),
// ldmatrix fragment loads. Both operands K-major:
//   C[M,N] = A[M,K] @ Bt[N,K]^T + bias[N]
// BM=BN=128, BK=32, stride 36 u32 (LDSM rows 16i mod 128 -> conflict-free).
// 256 threads = 8 warps (2m x 4n), warp tile 64x32.
// ---------------------------------------------------------------------------
#define TS_STRIDE 36
#define TSZ (128 * TS_STRIDE)
#define STG (2 * TSZ)
#define GEMM_SMEM (2 * STG * (int)sizeof(unsigned))   // 147456/2 = 73728*2? (= 2 stages)

template <bool OUT_TF32>
__global__ __launch_bounds__(256, 2) void gemm_tf32_cp_kernel(
    const unsigned* __restrict__ A, const unsigned* __restrict__ Bt,
    const float* __restrict__ bias, void* __restrict__ Cout,
    int M, int N, int K)
{
    extern __shared__ unsigned smem[];

    const int tid  = threadIdx.x;
    const int brow = blockIdx.y * 128;
    const int bcol = blockIdx.x * 128;

    const int warp = tid >> 5;
    const int lane = tid & 31;
    const int gid  = lane >> 2;
    const int tig  = lane & 3;
    const int wm0  = (warp & 1) * 64;
    const int wn0  = (warp >> 1) * 32;

    // ldmatrix lane addressing
    const int g    = lane >> 3;        // 0..3
    const int lrow = lane & 7;
    const int mrow = (g & 1) * 8 + lrow;    // row within 16-row block
    const int mcol = (g >> 1) * 4;          // 0 or 4

    // cp.async chunk coords (identical pattern for A and B tiles: 128x32)
    int rws[4], c4s[4];
#pragma unroll
    for (int i = 0; i < 4; i++) {
        int s = tid + i * 256;
        rws[i] = s >> 3;  c4s[i] = (s & 7) * 4;
    }

    float acc[4][4][4];
#pragma unroll
    for (int i = 0; i < 4; i++)
#pragma unroll
        for (int j = 0; j < 4; j++)
#pragma unroll
            for (int r = 0; r < 4; r++) acc[i][j][r] = 0.f;

    const int T = K >> 5;

    auto issue = [&](int t, int stage) {
        unsigned* As = smem + stage * STG;
        unsigned* Bs = As + TSZ;
        const int k0 = t << 5;
#pragma unroll
        for (int i = 0; i < 4; i++) {
            cp_async16((unsigned)__cvta_generic_to_shared(
                           &As[rws[i] * TS_STRIDE + c4s[i]]),
                       A + (size_t)(brow + rws[i]) * K + k0 + c4s[i]);
        }
#pragma unroll
        for (int i = 0; i < 4; i++) {
            cp_async16((unsigned)__cvta_generic_to_shared(
                           &Bs[rws[i] * TS_STRIDE + c4s[i]]),
                       Bt + (size_t)(bcol + rws[i]) * K + k0 + c4s[i]);
        }
        cp_commit();
    };

    issue(0, 0);

    for (int t = 0; t < T; t++) {
        const int cur = t & 1;
        if (t + 1 < T) {
            issue(t + 1, cur ^ 1);
            cp_wait<1>();
        } else {
            cp_wait<0>();
        }
        __syncthreads();

        unsigned* As = smem + cur * STG;
        unsigned* Bs = As + TSZ;
        const uint32_t As_u = (uint32_t)__cvta_generic_to_shared(As);
        const uint32_t Bs_u = (uint32_t)__cvta_generic_to_shared(Bs);

#pragma unroll
        for (int k8 = 0; k8 < 4; k8++) {
            const int kk = k8 * 8;
            unsigned a[4][4], b[4][2];
#pragma unroll
            for (int mi = 0; mi < 4; mi++) {
                uint32_t ad = As_u +
                    (uint32_t)(((wm0 + mi * 16 + mrow) * TS_STRIDE + kk + mcol) * 4);
                ldsm_x4(a[mi][0], a[mi][1], a[mi][2], a[mi][3], ad);
            }
#pragma unroll
            for (int p = 0; p < 2; p++) {
                uint32_t bd = Bs_u +
                    (uint32_t)(((wn0 + p * 16 + mrow) * TS_STRIDE + kk + mcol) * 4);
                unsigned r0, r1, r2, r3;
                ldsm_x4(r0, r1, r2, r3, bd);
                b[2 * p    ][0] = r0;  b[2 * p    ][1] = r2;
                b[2 * p + 1][0] = r1;  b[2 * p + 1][1] = r3;
            }
#pragma unroll
            for (int mi = 0; mi < 4; mi++)
#pragma unroll
                for (int ni = 0; ni < 4; ni++)
                    mma_tf32(acc[mi][ni][0], acc[mi][ni][1],
                             acc[mi][ni][2], acc[mi][ni][3],
                             a[mi][0], a[mi][1], a[mi][2], a[mi][3],
                             b[ni][0], b[ni][1]);
        }
        __syncthreads();
    }

    // ---- epilogue: bias + store ----
#pragma unroll
    for (int mi = 0; mi < 4; mi++) {
#pragma unroll
        for (int ni = 0; ni < 4; ni++) {
            int row0 = brow + wm0 + mi * 16 + gid;
            int col  = bcol + wn0 + ni * 8 + 2 * tig;
            float b0 = bias[col], b1 = bias[col + 1];
            float v00 = acc[mi][ni][0] + b0, v01 = acc[mi][ni][1] + b1;
            float v10 = acc[mi][ni][2] + b0, v11 = acc[mi][ni][3] + b1;
            if (OUT_TF32) {
                unsigned* C = (unsigned*)Cout;
                *(uint2*)(C + (size_t)row0 * N + col) =
                    make_uint2(f2tf32(v00), f2tf32(v01));
                *(uint2*)(C + (size_t)(row0 + 8) * N + col) =
                    make_uint2(f2tf32(v10), f2tf32(v11));
            } else {
                float* C = (float*)Cout;
                *(float2*)(C + (size_t)row0 * N + col)       = make_float2(v00, v01);
                *(float2*)(C + (size_t)(row0 + 8) * N + col) = make_float2(v10, v11);
            }
        }
    }
}

// ---------------------------------------------------------------------------
// Tensor-core flash attention — R14 structure (Q regs hoisted, cp.async K/V
// double-buffer, Ps smem staging). New: S-phase K fragments via ldmatrix.
// smem: 2x K[64][68] + 2x V[64][72] + Ps[128][68] = 106496 B -> 2 CTAs/SM.
// ---------------------------------------------------------------------------
#define QT      128
#define KT      64
#define KS_STR  68
#define VS_STR  72
#define PS_STR  68
#define ATTN_SMEM ((2 * KT * KS_STR + 2 * KT * VS_STR + QT * PS_STR) * (int)sizeof(unsigned))

__global__ __launch_bounds__(256, 2) void attn_mma_kernel(
    const unsigned* __restrict__ qkv, unsigned* __restrict__ y)
{
    extern __shared__ unsigned sm_u[];
    unsigned* Ks0 = sm_u;                       // 2 stages [64][68]
    unsigned* Vs0 = Ks0 + 2 * KT * KS_STR;      // 2 stages [64][72]
    unsigned* Ps  = Vs0 + 2 * KT * VS_STR;      // [128][68]; Q staging at start

    const int tid  = threadIdx.x;
    const int qt   = blockIdx.x;
    const int h    = blockIdx.y;
    const int b    = blockIdx.z;
    const int warp = tid >> 5;
    const int lane = tid & 31;
    const int gid  = lane >> 2;
    const int tig  = lane & 3;
    const int wq0  = warp * 16;

    const int g    = lane >> 3;
    const int lrow = lane & 7;
    const int mrow = (g & 1) * 8 + lrow;
    const int mcol = (g >> 1) * 4;

    const int kc_max = 2 * qt + 1;   // >= 1 always

    auto load_kv = [&](int kc, int st) {
        const unsigned* kb = qkv + (size_t)(b * SEQ + kc * KT) * C3 + EMB + h * HDIM;
        unsigned* Kd = Ks0 + st * (KT * KS_STR);
        unsigned* Vd = Vs0 + st * (KT * VS_STR);
#pragma unroll
        for (int i = 0; i < 4; i++) {
            int s   = tid + i * 256;
            int row = s >> 4;
            int c4  = (s & 15) * 4;
            cp_async16((unsigned)__cvta_generic_to_shared(Kd + row * KS_STR + c4),
                       kb + (size_t)row * C3 + c4);
            cp_async16((unsigned)__cvta_generic_to_shared(Vd + row * VS_STR + c4),
                       kb + EMB + (size_t)row * C3 + c4);
        }
        cp_commit();
    };
    load_kv(0, 0);
    load_kv(1, 1);

    // ---- stage Q tile into Ps, hoist A-fragments to regs ----
    const unsigned* qbase = qkv + (size_t)(b * SEQ + qt * QT) * C3 + h * HDIM;
#pragma unroll
    for (int i = 0; i < 8; i++) {
        int s   = tid + i * 256;
        int row = s >> 4;
        int c4  = (s & 15) * 4;
        *(uint4*)&Ps[row * PS_STR + c4] =
            *(const uint4*)(qbase + (size_t)row * C3 + c4);
    }
    __syncthreads();

    unsigned q[8][4];
    {
        const uint32_t Ps_u = (uint32_t)__cvta_generic_to_shared(Ps);
#pragma unroll
        for (int k8 = 0; k8 < 8; k8++) {
            uint32_t ad = Ps_u +
                (uint32_t)(((wq0 + mrow) * PS_STR + k8 * 8 + mcol) * 4);
            ldsm_x4(q[k8][0], q[k8][1], q[k8][2], q[k8][3], ad);
        }
    }
    // No barrier: Ps rows reused for P are warp-private.

    float o[8][4];
    float m[2], l[2];
#pragma unroll
    for (int t = 0; t < 8; t++)
#pragma unroll
        for (int r = 0; r < 4; r++) o[t][r] = 0.f;
    m[0] = m[1] = -1e30f;
    l[0] = l[1] = 0.f;

    const int qrow0 = qt * QT + wq0 + gid;
    const float SC = 0.18033688011112042f;   // 0.125 * log2(e)

    for (int kc = 0; kc <= kc_max; kc++) {
        const int st = kc & 1;
        if (kc < kc_max) cp_wait<1>();
        else             cp_wait<0>();
        __syncthreads();

        const unsigned* Kst = Ks0 + st * (KT * KS_STR);
        const unsigned* Vst = Vs0 + st * (KT * VS_STR);
        const uint32_t Ks_u = (uint32_t)__cvta_generic_to_shared(Kst);

        // ---- S = Q K^T (A regs; K frags via ldmatrix pairs) ----
        float s4[8][4];
#pragma unroll
        for (int t = 0; t < 8; t++)
#pragma unroll
            for (int r = 0; r < 4; r++) s4[t][r] = 0.f;

#pragma unroll
        for (int k8 = 0; k8 < 8; k8++) {
            const int kk = k8 * 8;
#pragma unroll
            for (int p = 0; p < 4; p++) {
                uint32_t kd = Ks_u +
                    (uint32_t)(((p * 16 + mrow) * KS_STR + kk + mcol) * 4);
                unsigned r0, r1, r2, r3;
                ldsm_x4(r0, r1, r2, r3, kd);
                mma_tf32(s4[2 * p][0], s4[2 * p][1], s4[2 * p][2], s4[2 * p][3],
                         q[k8][0], q[k8][1], q[k8][2], q[k8][3], r0, r2);
                mma_tf32(s4[2 * p + 1][0], s4[2 * p + 1][1],
                         s4[2 * p + 1][2], s4[2 * p + 1][3],
                         q[k8][0], q[k8][1], q[k8][2], q[k8][3], r1, r3);
            }
        }

        // ---- scale (log2 domain) + causal mask + online softmax ----
        const bool need_mask = (kc >= 2 * qt);
#pragma unroll
        for (int half = 0; half < 2; half++) {
            const int qi = qrow0 + half * 8;
            const int prow = wq0 + gid + half * 8;
            float tmax = -1e30f;
#pragma unroll
            for (int t = 0; t < 8; t++) {
                float v0 = s4[t][2 * half]     * SC;
                float v1 = s4[t][2 * half + 1] * SC;
                if (need_mask) {
                    int kj = kc * KT + t * 8 + 2 * tig;
                    if (kj     > qi) v0 = -1e30f;
                    if (kj + 1 > qi) v1 = -1e30f;
                }
                s4[t][2 * half]     = v0;
                s4[t][2 * half + 1] = v1;
                tmax = fmaxf(tmax, fmaxf(v0, v1));
            }
            tmax = fmaxf(tmax, __shfl_xor_sync(0xffffffffu, tmax, 1));
            tmax = fmaxf(tmax, __shfl_xor_sync(0xffffffffu, tmax, 2));

            float mnew = fmaxf(m[half], tmax);
            float corr = exp2f(m[half] - mnew);
            m[half] = mnew;
            float lsum = 0.f;
#pragma unroll
            for (int t = 0; t < 8; t++) {
                float p0 = exp2f(s4[t][2 * half]     - mnew);
                float p1 = exp2f(s4[t][2 * half + 1] - mnew);
                lsum += p0 + p1;
                Ps[prow * PS_STR + t * 8 + 2 * tig    ] = f2tf32(p0);
                Ps[prow * PS_STR + t * 8 + 2 * tig + 1] = f2tf32(p1);
            }
            lsum += __shfl_xor_sync(0xffffffffu, lsum, 1);
            lsum += __shfl_xor_sync(0xffffffffu, lsum, 2);
            l[half] = l[half] * corr + lsum;
#pragma unroll
            for (int t = 0; t < 8; t++) {
                o[t][2 * half]     *= corr;
                o[t][2 * half + 1] *= corr;
            }
        }
        __syncwarp();

        // ---- O += P @ V (P via ldmatrix from Ps; V scalar LDS) ----
        const uint32_t Ps_u = (uint32_t)__cvta_generic_to_shared(Ps);
#pragma unroll
        for (int k8 = 0; k8 < 8; k8++) {
            const int kk = k8 * 8;
            unsigned a0, a1, a2, a3;
            ldsm_x4(a0, a1, a2, a3,
                    Ps_u + (uint32_t)(((wq0 + mrow) * PS_STR + kk + mcol) * 4));
#pragma unroll
            for (int t = 0; t < 8; t++) {
                unsigned b0 = Vst[(kk + tig    ) * VS_STR + t * 8 + gid];
                unsigned b1 = Vst[(kk + tig + 4) * VS_STR + t * 8 + gid];
                mma_tf32(o[t][0], o[t][1], o[t][2], o[t][3],
                         a0, a1, a2, a3, b0, b1);
            }
        }

        __syncthreads();                       // all warps done with stage st
        if (kc + 2 <= kc_max) load_kv(kc + 2, st);
    }

    // ---- normalize + write y as tf32 ----
    const float inv0 = 1.f / l[0];
    const float inv1 = 1.f / l[1];
    unsigned* yb = y + (size_t)(b * SEQ + qt * QT) * EMB + h * HDIM;
#pragma unroll
    for (int t = 0; t < 8; t++) {
        int col = t * 8 + 2 * tig;
        *(uint2*)(yb + (size_t)(wq0 + gid    ) * EMB + col) =
            make_uint2(f2tf32(o[t][0] * inv0), f2tf32(o[t][1] * inv0));
        *(uint2*)(yb + (size_t)(wq0 + gid + 8) * EMB + col) =
            make_uint2(f2tf32(o[t][2] * inv1), f2tf32(o[t][3] * inv1));
    }
}

// ---------------------------------------------------------------------------
extern "C" void kernel_launch(void* const* d_in, const int* in_sizes, int n_in,
                              void* d_out, int out_size)
{
    const float* x      = (const float*)d_in[0];
    const float* W_attn = (const float*)d_in[1];
    const float* b_attn = (const float*)d_in[2];
    const float* W_proj = (const float*)d_in[3];
    const float* b_proj = (const float*)d_in[4];
    float* out = (float*)d_out;

    unsigned *qkv, *ybuf, *xa, *wa, *wp;
    cudaGetSymbolAddress((void**)&qkv,  g_qkv);
    cudaGetSymbolAddress((void**)&ybuf, g_y);
    cudaGetSymbolAddress((void**)&xa,   g_xa);
    cudaGetSymbolAddress((void**)&wa,   g_wa);
    cudaGetSymbolAddress((void**)&wp,   g_wp);

    // 0) pre-pass: x -> tf32; weights -> transposed tf32 ([N][K], K-major)
    {
        int n4x = ROWS * EMB / 4;
        cvt_tf32_kernel<<<(n4x + 255) / 256, 256>>>((const float4*)x, (uint4*)xa, n4x);
        dim3 blk(32, 8);
        transpose_tf32_kernel<<<dim3(C3 / 32, EMB / 32), blk>>>(W_attn, wa, EMB, C3);
        transpose_tf32_kernel<<<dim3(EMB / 32, EMB / 32), blk>>>(W_proj, wp, EMB, EMB);
    }

    // 1) qkv(tf32) = x @ W_attn + b_attn
    {
        cudaFuncSetAttribute(gemm_tf32_cp_kernel<true>,
                             cudaFuncAttributeMaxDynamicSharedMemorySize, GEMM_SMEM);
        dim3 grid(C3 / 128, ROWS / 128);
        gemm_tf32_cp_kernel<true><<<grid, 256, GEMM_SMEM>>>(
            xa, wa, b_attn, qkv, ROWS, C3, EMB);
    }

    // 2) tensor-core flash attention -> y(tf32)
    {
        cudaFuncSetAttribute(attn_mma_kernel,
                             cudaFuncAttributeMaxDynamicSharedMemorySize, ATTN_SMEM);
        dim3 grid(SEQ / QT, NHEAD, BATCH);
        attn_mma_kernel<<<grid, 256, ATTN_SMEM>>>(qkv, ybuf);
    }

    // 3) out = y @ W_proj + b_proj
    {
        cudaFuncSetAttribute(gemm_tf32_cp_kernel<false>,
                             cudaFuncAttributeMaxDynamicSharedMemorySize, GEMM_SMEM);
        dim3 grid(EMB / 128, ROWS / 128);
        gemm_tf32_cp_kernel<false><<<grid, 256, GEMM_SMEM>>>(
            ybuf, wp, b_proj, out, ROWS, EMB, EMB);
    }
}

// round 16
// speedup vs baseline: 1.0637x; 1.0637x over previous
#include <cuda_runtime.h>
#include <cstdint>

// Problem constants
#define BATCH 4
#define SEQ   2048
#define EMB   1024
#define NHEAD 16
#define HDIM  64
#define C3    3072
#define ROWS  8192   // BATCH*SEQ

// Scratch (device globals — allocation-free rule). tf32 values stored as u32.
__device__ unsigned g_qkv[(size_t)ROWS * C3];   // 96 MB (tf32)
__device__ unsigned g_y[(size_t)ROWS * EMB];    // 32 MB (tf32)
__device__ unsigned g_xa[(size_t)ROWS * EMB];   // 32 MB (tf32 of x)
__device__ unsigned g_wa[(size_t)EMB * C3];     // 12 MB (tf32 of W_attn)
__device__ unsigned g_wp[(size_t)EMB * EMB];    //  4 MB (tf32 of W_proj)

__device__ __forceinline__ unsigned f2tf32(float f) {
    unsigned r;
    asm("cvt.rna.tf32.f32 %0, %1;" : "=r"(r) : "f"(f));
    return r;
}

__device__ __forceinline__ void mma_tf32(
    float& c0, float& c1, float& c2, float& c3,
    unsigned a0, unsigned a1, unsigned a2, unsigned a3,
    unsigned b0, unsigned b1)
{
    asm volatile(
        "mma.sync.aligned.m16n8k8.row.col.f32.tf32.tf32.f32 "
        "{%0,%1,%2,%3}, {%4,%5,%6,%7}, {%8,%9}, {%0,%1,%2,%3};\n"
        : "+f"(c0), "+f"(c1), "+f"(c2), "+f"(c3)
        : "r"(a0), "r"(a1), "r"(a2), "r"(a3), "r"(b0), "r"(b1));
}

__device__ __forceinline__ void cp_async16(unsigned saddr, const void* g) {
    asm volatile("cp.async.cg.shared.global [%0], [%1], 16;\n"
                 :: "r"(saddr), "l"(g));
}
__device__ __forceinline__ void cp_commit() {
    asm volatile("cp.async.commit_group;\n");
}
template <int N>
__device__ __forceinline__ void cp_wait() {
    asm volatile("cp.async.wait_group %0;\n" :: "n"(N));
}

// ---------------------------------------------------------------------------
// One-time RNA tf32 conversion (fp32 -> tf32-in-u32)
// ---------------------------------------------------------------------------
__global__ void cvt_tf32_kernel(const float4* __restrict__ in,
                                uint4* __restrict__ out, int n4)
{
    int i = blockIdx.x * blockDim.x + threadIdx.x;
    if (i < n4) {
        float4 v = in[i];
        out[i] = make_uint4(f2tf32(v.x), f2tf32(v.y), f2tf32(v.z), f2tf32(v.w));
    }
}

// ---------------------------------------------------------------------------
// tf32 tensor-core GEMM with bias, cp.async 2-stage (R9-proven ordering).
// NEW: 128 threads = 4 warps (2m x 2n), warp tile 64x64 (4x8 mmas),
// __launch_bounds__(128, 2) -> 256 regs/thread so ptxas can software-
// pipeline fragment loads across k8 steps.
// C[M,N] = A[M,K] @ B[K,N] + bias[N].  A,B pre-converted tf32 (u32).
// BM=BN=128, BK=32.
// ---------------------------------------------------------------------------
#define AS_STRIDE 36
#define BS_STRIDE 136
#define ASZ (128 * AS_STRIDE)
#define BSZ (32 * BS_STRIDE)
#define STG (ASZ + BSZ)
#define GEMM_SMEM (2 * STG * (int)sizeof(unsigned))   // 71680 B

template <bool OUT_TF32>
__global__ __launch_bounds__(128, 2) void gemm_tf32_cp_kernel(
    const unsigned* __restrict__ A, const unsigned* __restrict__ B,
    const float* __restrict__ bias, void* __restrict__ Cout,
    int M, int N, int K)
{
    extern __shared__ unsigned smem[];

    const int tid  = threadIdx.x;
    const int brow = blockIdx.y * 128;
    const int bcol = blockIdx.x * 128;

    const int warp = tid >> 5;
    const int lane = tid & 31;
    const int gid  = lane >> 2;
    const int tig  = lane & 3;
    const int wm0  = (warp & 1) * 64;      // 2 warps in M
    const int wn0  = (warp >> 1) * 64;     // 2 warps in N (64-col slab)

    // cp.async chunk coordinates: A 1024 chunks, B 1024 chunks, 8 each/thread
    int a_row[8], a_c4[8], b_row[8], b_c4[8];
#pragma unroll
    for (int i = 0; i < 8; i++) {
        int s = tid + i * 128;
        a_row[i] = s >> 3;  a_c4[i] = (s & 7) * 4;    // A: 8 chunks / row of 32
        b_row[i] = s >> 5;  b_c4[i] = (s & 31) * 4;   // B: 32 chunks / row of 128
    }

    float acc[4][8][4];
#pragma unroll
    for (int i = 0; i < 4; i++)
#pragma unroll
        for (int j = 0; j < 8; j++)
#pragma unroll
            for (int r = 0; r < 4; r++) acc[i][j][r] = 0.f;

    const int T = K >> 5;

    auto issue = [&](int t, int stage) {
        unsigned* As = smem + stage * STG;
        unsigned* Bs = As + ASZ;
        const int k0 = t << 5;
#pragma unroll
        for (int i = 0; i < 8; i++) {
            cp_async16((unsigned)__cvta_generic_to_shared(
                           &As[a_row[i] * AS_STRIDE + a_c4[i]]),
                       A + (size_t)(brow + a_row[i]) * K + k0 + a_c4[i]);
        }
#pragma unroll
        for (int i = 0; i < 8; i++) {
            cp_async16((unsigned)__cvta_generic_to_shared(
                           &Bs[b_row[i] * BS_STRIDE + b_c4[i]]),
                       B + (size_t)(k0 + b_row[i]) * N + bcol + b_c4[i]);
        }
        cp_commit();
    };

    issue(0, 0);

    for (int t = 0; t < T; t++) {
        const int cur = t & 1;
        if (t + 1 < T) {
            issue(t + 1, cur ^ 1);
            cp_wait<1>();
        } else {
            cp_wait<0>();
        }
        __syncthreads();

        unsigned* As = smem + cur * STG;
        unsigned* Bs = As + ASZ;

#pragma unroll
        for (int k8 = 0; k8 < 4; k8++) {
            const int kk = k8 * 8;
            unsigned a[4][4], b[8][2];
#pragma unroll
            for (int mi = 0; mi < 4; mi++) {
                int r0 = wm0 + mi * 16 + gid;
                a[mi][0] = As[(r0    ) * AS_STRIDE + kk + tig];
                a[mi][1] = As[(r0 + 8) * AS_STRIDE + kk + tig];
                a[mi][2] = As[(r0    ) * AS_STRIDE + kk + tig + 4];
                a[mi][3] = As[(r0 + 8) * AS_STRIDE + kk + tig + 4];
            }
#pragma unroll
            for (int ni = 0; ni < 8; ni++) {
                int c0 = wn0 + ni * 8 + gid;
                b[ni][0] = Bs[(kk + tig    ) * BS_STRIDE + c0];
                b[ni][1] = Bs[(kk + tig + 4) * BS_STRIDE + c0];
            }
#pragma unroll
            for (int mi = 0; mi < 4; mi++)
#pragma unroll
                for (int ni = 0; ni < 8; ni++)
                    mma_tf32(acc[mi][ni][0], acc[mi][ni][1],
                             acc[mi][ni][2], acc[mi][ni][3],
                             a[mi][0], a[mi][1], a[mi][2], a[mi][3],
                             b[ni][0], b[ni][1]);
        }
        __syncthreads();
    }

    // ---- epilogue: bias + store ----
#pragma unroll
    for (int mi = 0; mi < 4; mi++) {
#pragma unroll
        for (int ni = 0; ni < 8; ni++) {
            int row0 = brow + wm0 + mi * 16 + gid;
            int col  = bcol + wn0 + ni * 8 + 2 * tig;
            float b0 = bias[col], b1 = bias[col + 1];
            float v00 = acc[mi][ni][0] + b0, v01 = acc[mi][ni][1] + b1;
            float v10 = acc[mi][ni][2] + b0, v11 = acc[mi][ni][3] + b1;
            if (OUT_TF32) {
                unsigned* C = (unsigned*)Cout;
                *(uint2*)(C + (size_t)row0 * N + col) =
                    make_uint2(f2tf32(v00), f2tf32(v01));
                *(uint2*)(C + (size_t)(row0 + 8) * N + col) =
                    make_uint2(f2tf32(v10), f2tf32(v11));
            } else {
                float* C = (float*)Cout;
                *(float2*)(C + (size_t)row0 * N + col)       = make_float2(v00, v01);
                *(float2*)(C + (size_t)(row0 + 8) * N + col) = make_float2(v10, v11);
            }
        }
    }
}

// ---------------------------------------------------------------------------
// Tensor-core flash attention — EXACT R14 kernel (proven best, ~330us):
// Q A-fragments hoisted to registers; K/V cp.async double-buffered;
// P staged via smem scalar stores (conflict-free strides).
// smem: 2x K[64][68] + 2x V[64][72] + Ps[128][68] = 106496 B -> 2 CTAs/SM.
// ---------------------------------------------------------------------------
#define QT      128
#define KT      64
#define KS_STR  68
#define VS_STR  72
#define PS_STR  68
#define ATTN_SMEM ((2 * KT * KS_STR + 2 * KT * VS_STR + QT * PS_STR) * (int)sizeof(unsigned))

__global__ __launch_bounds__(256, 2) void attn_mma_kernel(
    const unsigned* __restrict__ qkv, unsigned* __restrict__ y)
{
    extern __shared__ unsigned sm_u[];
    unsigned* Ks0 = sm_u;                       // 2 stages [64][68]
    unsigned* Vs0 = Ks0 + 2 * KT * KS_STR;      // 2 stages [64][72]
    unsigned* Ps  = Vs0 + 2 * KT * VS_STR;      // [128][68]; Q staging at start

    const int tid  = threadIdx.x;
    const int qt   = blockIdx.x;
    const int h    = blockIdx.y;
    const int b    = blockIdx.z;
    const int warp = tid >> 5;
    const int lane = tid & 31;
    const int gid  = lane >> 2;
    const int tig  = lane & 3;
    const int wq0  = warp * 16;

    const int kc_max = 2 * qt + 1;   // >= 1 always

    auto load_kv = [&](int kc, int st) {
        const unsigned* kb = qkv + (size_t)(b * SEQ + kc * KT) * C3 + EMB + h * HDIM;
        unsigned* Kd = Ks0 + st * (KT * KS_STR);
        unsigned* Vd = Vs0 + st * (KT * VS_STR);
#pragma unroll
        for (int i = 0; i < 4; i++) {
            int s   = tid + i * 256;
            int row = s >> 4;
            int c4  = (s & 15) * 4;
            cp_async16((unsigned)__cvta_generic_to_shared(Kd + row * KS_STR + c4),
                       kb + (size_t)row * C3 + c4);
            cp_async16((unsigned)__cvta_generic_to_shared(Vd + row * VS_STR + c4),
                       kb + EMB + (size_t)row * C3 + c4);
        }
        cp_commit();
    };
    load_kv(0, 0);
    load_kv(1, 1);

    // ---- stage Q tile (128x64) into Ps, then hoist A-fragments to regs ----
    const unsigned* qbase = qkv + (size_t)(b * SEQ + qt * QT) * C3 + h * HDIM;
#pragma unroll
    for (int i = 0; i < 8; i++) {
        int s   = tid + i * 256;
        int row = s >> 4;
        int c4  = (s & 15) * 4;
        *(uint4*)&Ps[row * PS_STR + c4] =
            *(const uint4*)(qbase + (size_t)row * C3 + c4);
    }
    __syncthreads();

    unsigned q[8][4];
#pragma unroll
    for (int k8 = 0; k8 < 8; k8++) {
        const int kk = k8 * 8;
        q[k8][0] = Ps[(wq0 + gid    ) * PS_STR + kk + tig];
        q[k8][1] = Ps[(wq0 + gid + 8) * PS_STR + kk + tig];
        q[k8][2] = Ps[(wq0 + gid    ) * PS_STR + kk + tig + 4];
        q[k8][3] = Ps[(wq0 + gid + 8) * PS_STR + kk + tig + 4];
    }
    // No barrier: Ps rows reused for P are warp-private.

    float o[8][4];
    float m[2], l[2];
#pragma unroll
    for (int t = 0; t < 8; t++)
#pragma unroll
        for (int r = 0; r < 4; r++) o[t][r] = 0.f;
    m[0] = m[1] = -1e30f;
    l[0] = l[1] = 0.f;

    const int qrow0 = qt * QT + wq0 + gid;
    const float SC = 0.18033688011112042f;   // 0.125 * log2(e)

    for (int kc = 0; kc <= kc_max; kc++) {
        const int st = kc & 1;
        if (kc < kc_max) cp_wait<1>();
        else             cp_wait<0>();
        __syncthreads();

        const unsigned* Kst = Ks0 + st * (KT * KS_STR);
        const unsigned* Vst = Vs0 + st * (KT * VS_STR);

        // ---- S = Q K^T (A from registers) ----
        float s4[8][4];
#pragma unroll
        for (int t = 0; t < 8; t++)
#pragma unroll
            for (int r = 0; r < 4; r++) s4[t][r] = 0.f;

#pragma unroll
        for (int k8 = 0; k8 < 8; k8++) {
            const int kk = k8 * 8;
#pragma unroll
            for (int t = 0; t < 8; t++) {
                unsigned b0 = Kst[(t * 8 + gid) * KS_STR + kk + tig];
                unsigned b1 = Kst[(t * 8 + gid) * KS_STR + kk + tig + 4];
                mma_tf32(s4[t][0], s4[t][1], s4[t][2], s4[t][3],
                         q[k8][0], q[k8][1], q[k8][2], q[k8][3], b0, b1);
            }
        }

        // ---- scale (log2 domain) + causal mask + online softmax ----
        const bool need_mask = (kc >= 2 * qt);
#pragma unroll
        for (int half = 0; half < 2; half++) {
            const int qi = qrow0 + half * 8;
            const int prow = wq0 + gid + half * 8;
            float tmax = -1e30f;
#pragma unroll
            for (int t = 0; t < 8; t++) {
                float v0 = s4[t][2 * half]     * SC;
                float v1 = s4[t][2 * half + 1] * SC;
                if (need_mask) {
                    int kj = kc * KT + t * 8 + 2 * tig;
                    if (kj     > qi) v0 = -1e30f;
                    if (kj + 1 > qi) v1 = -1e30f;
                }
                s4[t][2 * half]     = v0;
                s4[t][2 * half + 1] = v1;
                tmax = fmaxf(tmax, fmaxf(v0, v1));
            }
            tmax = fmaxf(tmax, __shfl_xor_sync(0xffffffffu, tmax, 1));
            tmax = fmaxf(tmax, __shfl_xor_sync(0xffffffffu, tmax, 2));

            float mnew = fmaxf(m[half], tmax);
            float corr = exp2f(m[half] - mnew);
            m[half] = mnew;
            float lsum = 0.f;
#pragma unroll
            for (int t = 0; t < 8; t++) {
                float p0 = exp2f(s4[t][2 * half]     - mnew);
                float p1 = exp2f(s4[t][2 * half + 1] - mnew);
                lsum += p0 + p1;
                Ps[prow * PS_STR + t * 8 + 2 * tig    ] = f2tf32(p0);
                Ps[prow * PS_STR + t * 8 + 2 * tig + 1] = f2tf32(p1);
            }
            lsum += __shfl_xor_sync(0xffffffffu, lsum, 1);
            lsum += __shfl_xor_sync(0xffffffffu, lsum, 2);
            l[half] = l[half] * corr + lsum;
#pragma unroll
            for (int t = 0; t < 8; t++) {
                o[t][2 * half]     *= corr;
                o[t][2 * half + 1] *= corr;
            }
        }
        __syncwarp();

        // ---- O += P @ V ----
#pragma unroll
        for (int k8 = 0; k8 < 8; k8++) {
            const int kk = k8 * 8;
            unsigned a0 = Ps[(wq0 + gid    ) * PS_STR + kk + tig];
            unsigned a1 = Ps[(wq0 + gid + 8) * PS_STR + kk + tig];
            unsigned a2 = Ps[(wq0 + gid    ) * PS_STR + kk + tig + 4];
            unsigned a3 = Ps[(wq0 + gid + 8) * PS_STR + kk + tig + 4];
#pragma unroll
            for (int t = 0; t < 8; t++) {
                unsigned b0 = Vst[(kk + tig    ) * VS_STR + t * 8 + gid];
                unsigned b1 = Vst[(kk + tig + 4) * VS_STR + t * 8 + gid];
                mma_tf32(o[t][0], o[t][1], o[t][2], o[t][3],
                         a0, a1, a2, a3, b0, b1);
            }
        }

        __syncthreads();                       // all warps done with stage st
        if (kc + 2 <= kc_max) load_kv(kc + 2, st);
    }

    // ---- normalize + write y as tf32 ----
    const float inv0 = 1.f / l[0];
    const float inv1 = 1.f / l[1];
    unsigned* yb = y + (size_t)(b * SEQ + qt * QT) * EMB + h * HDIM;
#pragma unroll
    for (int t = 0; t < 8; t++) {
        int col = t * 8 + 2 * tig;
        *(uint2*)(yb + (size_t)(wq0 + gid    ) * EMB + col) =
            make_uint2(f2tf32(o[t][0] * inv0), f2tf32(o[t][1] * inv0));
        *(uint2*)(yb + (size_t)(wq0 + gid + 8) * EMB + col) =
            make_uint2(f2tf32(o[t][2] * inv1), f2tf32(o[t][3] * inv1));
    }
}

// ---------------------------------------------------------------------------
extern "C" void kernel_launch(void* const* d_in, const int* in_sizes, int n_in,
                              void* d_out, int out_size)
{
    const float* x      = (const float*)d_in[0];
    const float* W_attn = (const float*)d_in[1];
    const float* b_attn = (const float*)d_in[2];
    const float* W_proj = (const float*)d_in[3];
    const float* b_proj = (const float*)d_in[4];
    float* out = (float*)d_out;

    unsigned *qkv, *ybuf, *xa, *wa, *wp;
    cudaGetSymbolAddress((void**)&qkv,  g_qkv);
    cudaGetSymbolAddress((void**)&ybuf, g_y);
    cudaGetSymbolAddress((void**)&xa,   g_xa);
    cudaGetSymbolAddress((void**)&wa,   g_wa);
    cudaGetSymbolAddress((void**)&wp,   g_wp);

    // 0) one-time RNA tf32 conversions
    {
        int n4x = ROWS * EMB / 4;
        cvt_tf32_kernel<<<(n4x + 255) / 256, 256>>>((const float4*)x, (uint4*)xa, n4x);
        int n4a = EMB * C3 / 4;
        cvt_tf32_kernel<<<(n4a + 255) / 256, 256>>>((const float4*)W_attn, (uint4*)wa, n4a);
        int n4p = EMB * EMB / 4;
        cvt_tf32_kernel<<<(n4p + 255) / 256, 256>>>((const float4*)W_proj, (uint4*)wp, n4p);
    }

    // 1) qkv(tf32) = x @ W_attn + b_attn
    {
        cudaFuncSetAttribute(gemm_tf32_cp_kernel<true>,
                             cudaFuncAttributeMaxDynamicSharedMemorySize, GEMM_SMEM);
        dim3 grid(C3 / 128, ROWS / 128);
        gemm_tf32_cp_kernel<true><<<grid, 128, GEMM_SMEM>>>(
            xa, wa, b_attn, qkv, ROWS, C3, EMB);
    }

    // 2) tensor-core flash attention -> y(tf32)
    {
        cudaFuncSetAttribute(attn_mma_kernel,
                             cudaFuncAttributeMaxDynamicSharedMemorySize, ATTN_SMEM);
        dim3 grid(SEQ / QT, NHEAD, BATCH);
        attn_mma_kernel<<<grid, 256, ATTN_SMEM>>>(qkv, ybuf);
    }

    // 3) out = y @ W_proj + b_proj
    {
        cudaFuncSetAttribute(gemm_tf32_cp_kernel<false>,
                             cudaFuncAttributeMaxDynamicSharedMemorySize, GEMM_SMEM);
        dim3 grid(EMB / 128, ROWS / 128);
        gemm_tf32_cp_kernel<false><<<grid, 128, GEMM_SMEM>>>(
            ybuf, wp, b_proj, out, ROWS, EMB, EMB);
    }
}